// round 14
// baseline (speedup 1.0000x reference)
#include <cuda_runtime.h>
#include <cuda_bf16.h>

// Problem constants
#define B_     8
#define H_     8
#define N1_    32
#define N2_    32
#define SLEN   1024          // N1*N2
#define HD     64            // head_dim = 512/8
#define NROWS  (B_*H_*SLEN)  // 65536 query rows

// Output layout: concatenation of flattened outputs in reference order
#define OFF_SINQ 0
#define CNT_SINQ (B_*H_*SLEN*HD)          // 4194304
#define OFF_COSQ (OFF_SINQ + CNT_SINQ)
#define OFF_SINK (OFF_COSQ + CNT_SINQ)    // 8388608
#define CNT_SINK (SLEN*HD)                // 65536
#define OFF_COSK (OFF_SINK + CNT_SINK)
#define OFF_MASK (OFF_COSK + CNT_SINK)    // 8519680

#define FULL 0xFFFFFFFFu

// ---------------------------------------------------------------------------
// HYBRID (best of R11 + R12), two warps per query row:
//  - row sums via closed-form geometric series (removes the 5-step chained
//    butterfly, ~130cyc -> ~60cyc of independent MUFU)   [from R12]
//  - mask epilogue via cheap independent broadcast SHFLs  [from R11]
// No smem, no barriers, default .wb stores.
// ---------------------------------------------------------------------------
__global__ __launch_bounds__(256, 8)
void k_row(const float* __restrict__ offsets,   // [B,H,N1,N2,2]
           const float* __restrict__ angle,     // [64]
           const float* __restrict__ decay,     // [8]
           float* __restrict__ out)
{
    const int wg   = (blockIdx.x * blockDim.x + threadIdx.x) >> 5;  // 0..2*NROWS-1
    const int lane = threadIdx.x & 31;
    const int row  = wg >> 1;
    const int half = wg & 1;
    const float fl = (float)lane;

    const int h = (row >> 10) & (H_-1);
    const int s = row & (SLEN-1);
    const int i = s >> 5;
    const int j = s & 31;

    const float2 off = __ldg(((const float2*)offsets) + row);
    const float a = (float)i + off.x;
    const float c = (float)j + off.y;
    const float L = __ldg(decay + h);

    // per-lane exponentials (feed the epilogue broadcasts)
    const float e1 = __expf(L * fabsf(a - fl));
    const float e2 = __expf(L * fabsf(c - fl));

    // closed-form row sums (no reduction): g = e^L, inv = 1/(1-g)
    // sum_l g^{|x-l|} = g^{x-k}(1-g^{k+1})/(1-g) + g^{k+1-x}(1-g^{31-k})/(1-g),
    //   k = clamp(floor(x), -1, 31); 1-g = 2^(-2-5h/8) is well-conditioned.
    const float g   = __expf(L);
    const float inv = __frcp_rn(1.0f - g);
    const float fk1 = fminf(fmaxf(floorf(a), -1.0f), 31.0f);
    const float fk2 = fminf(fmaxf(floorf(c), -1.0f), 31.0f);
    const float s1 = (__expf(L*(a - fk1))        * (1.0f - __expf(L*(fk1 + 1.0f)))
                   +  __expf(L*(fk1 + 1.0f - a)) * (1.0f - __expf(L*(31.0f - fk1)))) * inv;
    const float s2 = (__expf(L*(c - fk2))        * (1.0f - __expf(L*(fk2 + 1.0f)))
                   +  __expf(L*(fk2 + 1.0f - c)) * (1.0f - __expf(L*(31.0f - fk2)))) * inv;
    const float r = rsqrtf(s1 * s2);

    if (half == 0) {
        // sin_q / cos_q : 32 distinct phases (pairwise repeat). Lanes 0..15
        // each compute 2 adjacent distinct phases -> one float4 per array.
        if (lane < HD/4) {
            const float sa = a + c;
            float sv0, cv0, sv1, cv1;
            sincosf(sa * __ldg(angle + 4*lane),     &sv0, &cv0);
            sincosf(sa * __ldg(angle + 4*lane + 2), &sv1, &cv1);
            float4* sinq = (float4*)(out + OFF_SINQ) + (size_t)row * (HD/4);
            float4* cosq = (float4*)(out + OFF_COSQ) + (size_t)row * (HD/4);
            sinq[lane] = make_float4(sv0, sv0, sv1, sv1);
            cosq[lane] = make_float4(cv0, cv0, cv1, cv1);
        }
    } else if (row < SLEN) {
        // sin_k / cos_k : key-side row s, handled by the half==1 partner
        if (lane < HD/4) {
            const float sk = (float)(i + j);
            float sv0, cv0, sv1, cv1;
            sincosf(sk * __ldg(angle + 4*lane),     &sv0, &cv0);
            sincosf(sk * __ldg(angle + 4*lane + 2), &sv1, &cv1);
            float4* sink = (float4*)(out + OFF_SINK) + (size_t)row * (HD/4);
            float4* cosk = (float4*)(out + OFF_COSK) + (size_t)row * (HD/4);
            sink[lane] = make_float4(sv0, sv0, sv1, sv1);
            cosk[lane] = make_float4(cv0, cv0, cv1, cv1);
        }
    }

    // mask half-row: 512 floats = 4 float4/lane via broadcast shuffles.
    // float4 index (t,l): element = (t*32+l)*4, ki = t*4 + (l>>3), kj = (l&7)*4
    // this warp covers t in [half*4, half*4+4)
    const int base2 = (lane & 7) * 4;
    const float q0 = __shfl_sync(FULL, e2, base2 + 0);
    const float q1 = __shfl_sync(FULL, e2, base2 + 1);
    const float q2 = __shfl_sync(FULL, e2, base2 + 2);
    const float q3 = __shfl_sync(FULL, e2, base2 + 3);

    const int hi = lane >> 3;
    const int t0 = half * 4;
    float p[4];
    #pragma unroll
    for (int u = 0; u < 4; ++u)
        p[u] = r * __shfl_sync(FULL, e1, (t0 + u)*4 + hi);

    float4* mrow = (float4*)(out + OFF_MASK + (size_t)row * SLEN);
    #pragma unroll
    for (int u = 0; u < 4; ++u)
        mrow[(t0 + u)*32 + lane] = make_float4(p[u]*q0, p[u]*q1, p[u]*q2, p[u]*q3);
}

extern "C" void kernel_launch(void* const* d_in, const int* in_sizes, int n_in,
                              void* d_out, int out_size)
{
    const float* offsets = nullptr;
    const float* angle   = nullptr;
    const float* decay   = nullptr;
    for (int k = 0; k < n_in; ++k) {
        if      (in_sizes[k] == B_*H_*N1_*N2_*2) offsets = (const float*)d_in[k];
        else if (in_sizes[k] == HD)              angle   = (const float*)d_in[k];
        else if (in_sizes[k] == H_)              decay   = (const float*)d_in[k];
    }
    float* out = (float*)d_out;

    // two warps per row: 131072 warps = 16384 blocks of 256 threads
    k_row<<<2*NROWS/8, 256>>>(offsets, angle, decay, out);
}

// round 15
// speedup vs baseline: 1.3959x; 1.3959x over previous
#include <cuda_runtime.h>
#include <cuda_bf16.h>

// Problem constants
#define B_     8
#define H_     8
#define N1_    32
#define N2_    32
#define SLEN   1024          // N1*N2
#define HD     64            // head_dim = 512/8
#define NROWS  (B_*H_*SLEN)  // 65536 query rows

// Output layout: concatenation of flattened outputs in reference order
#define OFF_SINQ 0
#define CNT_SINQ (B_*H_*SLEN*HD)          // 4194304
#define OFF_COSQ (OFF_SINQ + CNT_SINQ)
#define OFF_SINK (OFF_COSQ + CNT_SINQ)    // 8388608
#define CNT_SINK (SLEN*HD)                // 65536
#define OFF_COSK (OFF_SINK + CNT_SINK)
#define OFF_MASK (OFF_COSK + CNT_SINK)    // 8519680

#define FULL 0xFFFFFFFFu

// ---------------------------------------------------------------------------
// FINAL (converged): TWO warps per query row (131072 warps).
// Measured design-space bracket (kernel time):
//   warps/row:  1 -> 43.6us,  2 -> 42.1us (BEST),  4 -> 48.1us, persistent -> 52.8us
//   stores:     .wb best (.cs -> +1.0us)
//   reduction:  butterfly best (closed-form -> +0.9us, hybrid -> +20us via
//               MIO/L1tex contention between SHFL and STG)
// Each warp duplicates the cheap prologue (exp + shuffle reductions) and
// writes half of the 4 KB mask row. Pair member 0 writes sin_q/cos_q;
// member 1 writes sin_k/cos_k for rows < 1024. No smem, no barriers.
// DRAM 73% / ~7.2 TB/s effective — at the measured LTS/store ceiling.
// ---------------------------------------------------------------------------
__global__ __launch_bounds__(256, 8)
void k_row(const float* __restrict__ offsets,   // [B,H,N1,N2,2]
           const float* __restrict__ angle,     // [64]
           const float* __restrict__ decay,     // [8]
           float* __restrict__ out)
{
    const int wg   = (blockIdx.x * blockDim.x + threadIdx.x) >> 5;  // 0..2*NROWS-1
    const int lane = threadIdx.x & 31;
    const int row  = wg >> 1;
    const int half = wg & 1;
    const float fl = (float)lane;

    const int h = (row >> 10) & (H_-1);
    const int s = row & (SLEN-1);
    const int i = s >> 5;
    const int j = s & 31;

    const float2 off = __ldg(((const float2*)offsets) + row);
    const float a = (float)i + off.x;
    const float c = (float)j + off.y;
    const float L = __ldg(decay + h);

    // per-lane exponentials
    float e1 = __expf(L * fabsf(a - fl));
    float e2 = __expf(L * fabsf(c - fl));

    // warp sums (combined butterfly)
    float s1 = e1, s2 = e2;
    #pragma unroll
    for (int o = 16; o > 0; o >>= 1) {
        s1 += __shfl_xor_sync(FULL, s1, o);
        s2 += __shfl_xor_sync(FULL, s2, o);
    }
    const float r = rsqrtf(s1 * s2);

    if (half == 0) {
        // sin_q / cos_q : 32 distinct phases (pairwise repeat). Lanes 0..15
        // each compute 2 adjacent distinct phases -> one float4 per array.
        if (lane < HD/4) {
            const float sa = a + c;
            float sv0, cv0, sv1, cv1;
            sincosf(sa * __ldg(angle + 4*lane),     &sv0, &cv0);
            sincosf(sa * __ldg(angle + 4*lane + 2), &sv1, &cv1);
            float4* sinq = (float4*)(out + OFF_SINQ) + (size_t)row * (HD/4);
            float4* cosq = (float4*)(out + OFF_COSQ) + (size_t)row * (HD/4);
            sinq[lane] = make_float4(sv0, sv0, sv1, sv1);
            cosq[lane] = make_float4(cv0, cv0, cv1, cv1);
        }
    } else if (row < SLEN) {
        // sin_k / cos_k : key-side row s, handled by the half==1 partner
        if (lane < HD/4) {
            const float sk = (float)(i + j);
            float sv0, cv0, sv1, cv1;
            sincosf(sk * __ldg(angle + 4*lane),     &sv0, &cv0);
            sincosf(sk * __ldg(angle + 4*lane + 2), &sv1, &cv1);
            float4* sink = (float4*)(out + OFF_SINK) + (size_t)row * (HD/4);
            float4* cosk = (float4*)(out + OFF_COSK) + (size_t)row * (HD/4);
            sink[lane] = make_float4(sv0, sv0, sv1, sv1);
            cosk[lane] = make_float4(cv0, cv0, cv1, cv1);
        }
    }

    // mask half-row: 512 floats = 4 float4/lane.
    // float4 index (t,l): element = (t*32+l)*4, ki = t*4 + (l>>3), kj = (l&7)*4
    // this warp covers t in [half*4, half*4+4)
    const int base2 = (lane & 7) * 4;
    const float q0 = __shfl_sync(FULL, e2, base2 + 0);
    const float q1 = __shfl_sync(FULL, e2, base2 + 1);
    const float q2 = __shfl_sync(FULL, e2, base2 + 2);
    const float q3 = __shfl_sync(FULL, e2, base2 + 3);

    const int hi = lane >> 3;
    const int t0 = half * 4;
    float p[4];
    #pragma unroll
    for (int u = 0; u < 4; ++u)
        p[u] = r * __shfl_sync(FULL, e1, (t0 + u)*4 + hi);

    float4* mrow = (float4*)(out + OFF_MASK + (size_t)row * SLEN);
    #pragma unroll
    for (int u = 0; u < 4; ++u)
        mrow[(t0 + u)*32 + lane] = make_float4(p[u]*q0, p[u]*q1, p[u]*q2, p[u]*q3);
}

extern "C" void kernel_launch(void* const* d_in, const int* in_sizes, int n_in,
                              void* d_out, int out_size)
{
    const float* offsets = nullptr;
    const float* angle   = nullptr;
    const float* decay   = nullptr;
    for (int k = 0; k < n_in; ++k) {
        if      (in_sizes[k] == B_*H_*N1_*N2_*2) offsets = (const float*)d_in[k];
        else if (in_sizes[k] == HD)              angle   = (const float*)d_in[k];
        else if (in_sizes[k] == H_)              decay   = (const float*)d_in[k];
    }
    float* out = (float*)d_out;

    // two warps per row: 131072 warps = 16384 blocks of 256 threads
    k_row<<<2*NROWS/8, 256>>>(offsets, angle, decay, out);
}

// round 17
// speedup vs baseline: 1.4187x; 1.0163x over previous
#include <cuda_runtime.h>
#include <cuda_bf16.h>

// Problem constants
#define B_     8
#define H_     8
#define N1_    32
#define N2_    32
#define SLEN   1024          // N1*N2
#define HD     64            // head_dim = 512/8
#define NROWS  (B_*H_*SLEN)  // 65536 query rows

// Output layout: concatenation of flattened outputs in reference order
#define OFF_SINQ 0
#define CNT_SINQ (B_*H_*SLEN*HD)          // 4194304
#define OFF_COSQ (OFF_SINQ + CNT_SINQ)
#define OFF_SINK (OFF_COSQ + CNT_SINQ)    // 8388608
#define CNT_SINK (SLEN*HD)                // 65536
#define OFF_COSK (OFF_SINK + CNT_SINK)
#define OFF_MASK (OFF_COSK + CNT_SINK)    // 8519680

#define FULL 0xFFFFFFFFu

// ---------------------------------------------------------------------------
// TWO warps per query row (measured optimum), STORE-FIRST ordering:
// the 4 mask STG.128s (93% of payload) issue immediately after the butterfly
// reduction; the small sincos tail (lanes<16, 2 STG.128) overlaps the store
// drain instead of delaying the burst.
// Bracketed design space (kernel us): warps/row 1/2/4/persist = 43.6/42.1/
// 48.1/52.8; .cs stores +1.0; closed-form sums +0.9; hybrid +20 (MIO clash).
// ---------------------------------------------------------------------------
__global__ __launch_bounds__(256, 8)
void k_row(const float* __restrict__ offsets,   // [B,H,N1,N2,2]
           const float* __restrict__ angle,     // [64]
           const float* __restrict__ decay,     // [8]
           float* __restrict__ out)
{
    const int wg   = (blockIdx.x * blockDim.x + threadIdx.x) >> 5;  // 0..2*NROWS-1
    const int lane = threadIdx.x & 31;
    const int row  = wg >> 1;
    const int half = wg & 1;
    const float fl = (float)lane;

    const int h = (row >> 10) & (H_-1);
    const int s = row & (SLEN-1);
    const int i = s >> 5;
    const int j = s & 31;

    const float2 off = __ldg(((const float2*)offsets) + row);
    const float a = (float)i + off.x;
    const float c = (float)j + off.y;
    const float L = __ldg(decay + h);

    // per-lane exponentials
    float e1 = __expf(L * fabsf(a - fl));
    float e2 = __expf(L * fabsf(c - fl));

    // warp sums (combined butterfly)
    float s1 = e1, s2 = e2;
    #pragma unroll
    for (int o = 16; o > 0; o >>= 1) {
        s1 += __shfl_xor_sync(FULL, s1, o);
        s2 += __shfl_xor_sync(FULL, s2, o);
    }
    const float r = rsqrtf(s1 * s2);

    // ---- mask half-row FIRST: 512 floats = 4 float4/lane ----
    // float4 index (t,l): element = (t*32+l)*4, ki = t*4 + (l>>3), kj = (l&7)*4
    // this warp covers t in [half*4, half*4+4)
    const int base2 = (lane & 7) * 4;
    const float q0 = __shfl_sync(FULL, e2, base2 + 0);
    const float q1 = __shfl_sync(FULL, e2, base2 + 1);
    const float q2 = __shfl_sync(FULL, e2, base2 + 2);
    const float q3 = __shfl_sync(FULL, e2, base2 + 3);

    const int hi = lane >> 3;
    const int t0 = half * 4;
    float p[4];
    #pragma unroll
    for (int u = 0; u < 4; ++u)
        p[u] = r * __shfl_sync(FULL, e1, (t0 + u)*4 + hi);

    float4* mrow = (float4*)(out + OFF_MASK + (size_t)row * SLEN);
    #pragma unroll
    for (int u = 0; u < 4; ++u)
        mrow[(t0 + u)*32 + lane] = make_float4(p[u]*q0, p[u]*q1, p[u]*q2, p[u]*q3);

    // ---- sincos tail overlaps store drain ----
    if (half == 0) {
        // sin_q / cos_q : 32 distinct phases (pairwise repeat). Lanes 0..15
        // each compute 2 adjacent distinct phases -> one float4 per array.
        if (lane < HD/4) {
            const float sa = a + c;
            float sv0, cv0, sv1, cv1;
            sincosf(sa * __ldg(angle + 4*lane),     &sv0, &cv0);
            sincosf(sa * __ldg(angle + 4*lane + 2), &sv1, &cv1);
            float4* sinq = (float4*)(out + OFF_SINQ) + (size_t)row * (HD/4);
            float4* cosq = (float4*)(out + OFF_COSQ) + (size_t)row * (HD/4);
            sinq[lane] = make_float4(sv0, sv0, sv1, sv1);
            cosq[lane] = make_float4(cv0, cv0, cv1, cv1);
        }
    } else if (row < SLEN) {
        // sin_k / cos_k : key-side row s, handled by the half==1 partner
        if (lane < HD/4) {
            const float sk = (float)(i + j);
            float sv0, cv0, sv1, cv1;
            sincosf(sk * __ldg(angle + 4*lane),     &sv0, &cv0);
            sincosf(sk * __ldg(angle + 4*lane + 2), &sv1, &cv1);
            float4* sink = (float4*)(out + OFF_SINK) + (size_t)row * (HD/4);
            float4* cosk = (float4*)(out + OFF_COSK) + (size_t)row * (HD/4);
            sink[lane] = make_float4(sv0, sv0, sv1, sv1);
            cosk[lane] = make_float4(cv0, cv0, cv1, cv1);
        }
    }
}

extern "C" void kernel_launch(void* const* d_in, const int* in_sizes, int n_in,
                              void* d_out, int out_size)
{
    const float* offsets = nullptr;
    const float* angle   = nullptr;
    const float* decay   = nullptr;
    for (int k = 0; k < n_in; ++k) {
        if      (in_sizes[k] == B_*H_*N1_*N2_*2) offsets = (const float*)d_in[k];
        else if (in_sizes[k] == HD)              angle   = (const float*)d_in[k];
        else if (in_sizes[k] == H_)              decay   = (const float*)d_in[k];
    }
    float* out = (float*)d_out;

    // two warps per row: 131072 warps = 16384 blocks of 256 threads
    k_row<<<2*NROWS/8, 256>>>(offsets, angle, decay, out);
}